// round 12
// baseline (speedup 1.0000x reference)
#include <cuda_runtime.h>

#define HH   512
#define WW   512
#define HWSZ (HH * WW)
#define CIN  32
#define COUT 24
#define NP   8
#define CHB  12   // channels per CTA

typedef unsigned long long u64;

__device__ __forceinline__ u64 fma2_(u64 a, u64 b, u64 c) {
    u64 d; asm("fma.rn.f32x2 %0, %1, %2, %3;" : "=l"(d) : "l"(a), "l"(b), "l"(c)); return d;
}
__device__ __forceinline__ u64 add2_(u64 a, u64 b) {
    u64 d; asm("add.rn.f32x2 %0, %1, %2;" : "=l"(d) : "l"(a), "l"(b)); return d;
}
__device__ __forceinline__ u64 mul2_(u64 a, u64 b) {
    u64 d; asm("mul.rn.f32x2 %0, %1, %2;" : "=l"(d) : "l"(a), "l"(b)); return d;
}
__device__ __forceinline__ u64 pack2_(float lo, float hi) {
    u64 r; asm("mov.b64 %0, {%1, %2};" : "=l"(r) : "f"(lo), "f"(hi)); return r;
}
__device__ __forceinline__ float2 unpack2_(u64 v) {
    float lo, hi; asm("mov.b64 {%0, %1}, %2;" : "=f"(lo), "=f"(hi) : "l"(v));
    return make_float2(lo, hi);
}

#define M1C 0xBF800000BF800000ull   /* (-1.0f, -1.0f) */

// 8 px/thread: window [x0-4, x0+11] = 16 floats = 4 aligned LDG.128 serving
// 5 taps x 8 px -> 2 floats of crossbar delivery per pixel-tap-row (vs 3 at
// 4 px/thread): ~33% less L1 wavefront traffic, the measured wall. Tap pair
// for px-pair j at dx is vp[j+dx]. 12 channels per CTA (acc fits registers);
// d2/exp duplicated across the 2 channel-groups (FMA pipe has headroom).
// Fused single pass, dy fully unrolled, no launch cap (regs = MLP budget).
__global__ void __launch_bounds__(128) bilat_kernel(
    const float* __restrict__ inp, const float* __restrict__ par,
    float* __restrict__ out)
{
    const int lane = threadIdx.x & 31;
    const int ty   = threadIdx.x >> 5;
    const int x0   = blockIdx.x * 256 + lane * 8;
    const int y    = blockIdx.y * 4 + ty;
    const int b    = blockIdx.z >> 1;
    const int h    = blockIdx.z & 1;

    const float* __restrict__ parb = par + b * (NP * HWSZ);
    const float* __restrict__ inpb = inp + b * (CIN * HWSZ) + h * (CHB * HWSZ);
    float* __restrict__ outb = out + b * (COUT * HWSZ) + h * (CHB * HWSZ);

    const int xA = max(x0 - 4, 0);          // clamped; OOB-shifted slots masked
    const int xB = x0;
    const int xC = x0 + 4;
    const int xD = min(x0 + 8, WW - 4);

    const int cbase = y * WW + x0;

    u64 acc[CHB][4];
#pragma unroll
    for (int c = 0; c < CHB; ++c)
#pragma unroll
        for (int j = 0; j < 4; ++j) acc[c][j] = 0ull;
    u64 ws[4] = { 0ull, 0ull, 0ull, 0ull };

#pragma unroll
    for (int dy = 0; dy < 5; ++dy) {
        const int   ny = y + dy * 2 - 4;
        const float mr = ((unsigned)ny < (unsigned)HH) ? 1.0f : 0.0f;
        const int   ro = min(max(ny, 0), HH - 1) * WW;

        // ---- squared param distances: 8 px (4 pairs) x 5 dx ----
        u64 d2[5][4];
#pragma unroll
        for (int dx = 0; dx < 5; ++dx)
#pragma unroll
            for (int j = 0; j < 4; ++j) d2[dx][j] = 0ull;

#pragma unroll
        for (int p = 0; p < NP; ++p) {
            const float* pr = parb + p * HWSZ;
            ulonglong2 c0 = __ldg(reinterpret_cast<const ulonglong2*>(pr + cbase));
            ulonglong2 c1 = __ldg(reinterpret_cast<const ulonglong2*>(pr + cbase + 4));
            u64 cc[4] = { c0.x, c0.y, c1.x, c1.y };
            ulonglong2 l0 = __ldg(reinterpret_cast<const ulonglong2*>(pr + ro + xA));
            ulonglong2 l1 = __ldg(reinterpret_cast<const ulonglong2*>(pr + ro + xB));
            ulonglong2 l2 = __ldg(reinterpret_cast<const ulonglong2*>(pr + ro + xC));
            ulonglong2 l3 = __ldg(reinterpret_cast<const ulonglong2*>(pr + ro + xD));
            u64 vp[8] = { l0.x, l0.y, l1.x, l1.y, l2.x, l2.y, l3.x, l3.y };
#pragma unroll
            for (int dx = 0; dx < 5; ++dx)
#pragma unroll
                for (int j = 0; j < 4; ++j) {
                    u64 t = fma2_(vp[j + dx], M1C, cc[j]);   // neighbor - center
                    d2[dx][j] = fma2_(t, t, d2[dx][j]);
                }
        }

        // ---- weights: exp(-d2) * mask (masks recomputed, ALU pipe idle) ----
        u64 w[5][4];
#pragma unroll
        for (int dx = 0; dx < 5; ++dx)
#pragma unroll
            for (int j = 0; j < 4; ++j) {
                const int g = x0 + 2 * j + 2 * dx - 4;  // global x of px 2j's tap
                const float m0 = ((unsigned)(g + 0) < (unsigned)WW) ? mr : 0.0f;
                const float m1 = ((unsigned)(g + 1) < (unsigned)WW) ? mr : 0.0f;
                float2 a = unpack2_(d2[dx][j]);
                u64 e = mul2_(pack2_(__expf(-a.x), __expf(-a.y)), pack2_(m0, m1));
                w[dx][j] = e;
                ws[j] = add2_(ws[j], e);
            }

        // ---- 12-channel accumulate ----
#pragma unroll
        for (int ch = 0; ch < CHB; ++ch) {
            const float* ir = inpb + ch * HWSZ + ro;
            ulonglong2 l0 = __ldg(reinterpret_cast<const ulonglong2*>(ir + xA));
            ulonglong2 l1 = __ldg(reinterpret_cast<const ulonglong2*>(ir + xB));
            ulonglong2 l2 = __ldg(reinterpret_cast<const ulonglong2*>(ir + xC));
            ulonglong2 l3 = __ldg(reinterpret_cast<const ulonglong2*>(ir + xD));
            u64 vp[8] = { l0.x, l0.y, l1.x, l1.y, l2.x, l2.y, l3.x, l3.y };
#pragma unroll
            for (int dx = 0; dx < 5; ++dx)
#pragma unroll
                for (int j = 0; j < 4; ++j)
                    acc[ch][j] = fma2_(w[dx][j], vp[j + dx], acc[ch][j]);
        }
    }

    // ---- normalize once at the store ----
    u64 r[4];
#pragma unroll
    for (int j = 0; j < 4; ++j) {
        float2 s = unpack2_(ws[j]);
        r[j] = pack2_(__fdividef(1.0f, s.x + 1e-8f),
                      __fdividef(1.0f, s.y + 1e-8f));
    }

#pragma unroll
    for (int ch = 0; ch < CHB; ++ch) {
        float2 f0 = unpack2_(mul2_(acc[ch][0], r[0]));
        float2 f1 = unpack2_(mul2_(acc[ch][1], r[1]));
        float2 f2 = unpack2_(mul2_(acc[ch][2], r[2]));
        float2 f3 = unpack2_(mul2_(acc[ch][3], r[3]));
        float* op = outb + ch * HWSZ + cbase;
        *reinterpret_cast<float4*>(op)     = make_float4(f0.x, f0.y, f1.x, f1.y);
        *reinterpret_cast<float4*>(op + 4) = make_float4(f2.x, f2.y, f3.x, f3.y);
    }
}

extern "C" void kernel_launch(void* const* d_in, const int* in_sizes, int n_in,
                              void* d_out, int out_size)
{
    const float* inp = (const float*)d_in[0];   // (4,32,512,512) f32
    const float* par = (const float*)d_in[1];   // (4, 8,512,512) f32
    if (n_in >= 2 && in_sizes[0] < in_sizes[1]) {
        const float* t = inp; inp = par; par = t;
    }
    float* out = (float*)d_out;                 // (4,24,512,512) f32

    dim3 grid(WW / 256, HH / 4, 4 * 2);         // x-tiles, 4-row bands, batch x ch-half
    dim3 block(128);
    bilat_kernel<<<grid, block>>>(inp, par, out);
}

// round 13
// speedup vs baseline: 1.5858x; 1.5858x over previous
#include <cuda_runtime.h>

#define HH    512
#define WW    512
#define HWSZ  (HH * WW)
#define CIN   32
#define COUT  24
#define NP    8
#define RPC   8      // output rows per CTA
#define KR    16     // staged input rows per CTA (RPC + 2*4)
#define PITCH 136    // floats per staged row ([tileX-4, tileX+131])
#define NCHK  34     // 16B chunks per row
#define SMEM_BYTES (COUT * KR * PITCH * 4)   // 208896 B

typedef unsigned long long u64;

__device__ __forceinline__ u64 fma2_(u64 a, u64 b, u64 c) {
    u64 d; asm("fma.rn.f32x2 %0, %1, %2, %3;" : "=l"(d) : "l"(a), "l"(b), "l"(c)); return d;
}
__device__ __forceinline__ u64 add2_(u64 a, u64 b) {
    u64 d; asm("add.rn.f32x2 %0, %1, %2;" : "=l"(d) : "l"(a), "l"(b)); return d;
}
__device__ __forceinline__ u64 mul2_(u64 a, u64 b) {
    u64 d; asm("mul.rn.f32x2 %0, %1, %2;" : "=l"(d) : "l"(a), "l"(b)); return d;
}
__device__ __forceinline__ u64 pack2_(float lo, float hi) {
    u64 r; asm("mov.b64 %0, {%1, %2};" : "=l"(r) : "f"(lo), "f"(hi)); return r;
}
__device__ __forceinline__ float2 unpack2_(u64 v) {
    float lo, hi; asm("mov.b64 {%0, %1}, %2;" : "=f"(lo), "=f"(hi) : "l"(v));
    return make_float2(lo, hi);
}

#define M1C 0xBF800000BF800000ull   /* (-1.0f, -1.0f) */

// Channel stream staged through SMEM via cp.async (no register destination,
// unbounded MLP): CTA = 8 output rows x 128 px; its 16 distinct tap rows x
// 24 channels (204KB) are filled once, then consumed as conflict-free
// LDS.128 (29-cyc latency, fully covered). Params/centers stay direct LDG
// (hoisted centers), hidden under channel FMA. Live regs ~170 -> no spills.
__global__ void __launch_bounds__(256) bilat_kernel(
    const float* __restrict__ inp, const float* __restrict__ par,
    float* __restrict__ out)
{
    extern __shared__ float sm[];

    const int tid   = threadIdx.x;
    const int lane  = tid & 31;
    const int wid   = tid >> 5;
    const int tileX = blockIdx.x * 128;
    const int x0    = tileX + lane * 4;
    const int y0    = blockIdx.y * RPC;
    const int y     = y0 + wid;
    const int b     = blockIdx.z;

    const float* __restrict__ parb = par + b * (NP * HWSZ);
    const float* __restrict__ inpb = inp + b * (CIN * HWSZ);
    float* __restrict__ outb = out + b * (COUT * HWSZ);

    // ---- fill: 24 ch x 16 rows x 34 aligned 16B chunks via cp.async ----
    {
        const unsigned sbase = (unsigned)__cvta_generic_to_shared(sm);
#pragma unroll 4
        for (int c = tid; c < COUT * KR * NCHK; c += 256) {
            const int ch  = c / (KR * NCHK);
            const int rem = c - ch * (KR * NCHK);
            const int row = rem / NCHK;
            const int i   = rem - row * NCHK;
            const int gx  = min(max(tileX - 4 + i * 4, 0), WW - 4);   // clamped; OOB taps masked later
            const int gy  = min(max(y0 - 4 + row, 0), HH - 1);
            const float* src = inpb + ch * HWSZ + gy * WW + gx;
            const unsigned dst = sbase + (unsigned)(((ch * KR + row) * PITCH + i * 4) * 4);
            asm volatile("cp.async.cg.shared.global [%0], [%1], 16;" :: "r"(dst), "l"(src));
        }
        asm volatile("cp.async.commit_group;");
    }

    // ---- hoisted center params (independent of staging) ----
    const int cbase = y * WW + x0;
    u64 ccx[NP], ccy[NP];
#pragma unroll
    for (int p = 0; p < NP; ++p) {
        ulonglong2 cc = __ldg(reinterpret_cast<const ulonglong2*>(parb + p * HWSZ + cbase));
        ccx[p] = cc.x; ccy[p] = cc.y;
    }

    // x-direction OOB masks
    u64 mX[5][2];
#pragma unroll
    for (int dx = 0; dx < 5; ++dx) {
        const int g = x0 + dx * 2 - 4;
        mX[dx][0] = pack2_(((unsigned)(g + 0) < (unsigned)WW) ? 1.0f : 0.0f,
                           ((unsigned)(g + 1) < (unsigned)WW) ? 1.0f : 0.0f);
        mX[dx][1] = pack2_(((unsigned)(g + 2) < (unsigned)WW) ? 1.0f : 0.0f,
                           ((unsigned)(g + 3) < (unsigned)WW) ? 1.0f : 0.0f);
    }

    const int xa = max(x0 - 4, 0);
    const int xb = x0;
    const int xc = min(x0 + 4, WW - 4);

    u64 acc[COUT][2];
#pragma unroll
    for (int c = 0; c < COUT; ++c) { acc[c][0] = 0ull; acc[c][1] = 0ull; }
    u64 ws0 = 0ull, ws1 = 0ull;

    asm volatile("cp.async.wait_group 0;");
    __syncthreads();

#pragma unroll
    for (int dy = 0; dy < 5; ++dy) {
        const int   ny = y + dy * 2 - 4;
        const float mr = ((unsigned)ny < (unsigned)HH) ? 1.0f : 0.0f;
        const int   ro = min(max(ny, 0), HH - 1) * WW;
        const int   k  = wid + 2 * dy;          // staged row index for this warp/dy

        // ---- squared param distances (direct LDG, hidden under LDS compute) ----
        u64 d2[5][2];
#pragma unroll
        for (int dx = 0; dx < 5; ++dx) { d2[dx][0] = 0ull; d2[dx][1] = 0ull; }

#pragma unroll
        for (int p = 0; p < NP; ++p) {
            const float* pr = parb + p * HWSZ;
            ulonglong2 l0 = __ldg(reinterpret_cast<const ulonglong2*>(pr + ro + xa));
            ulonglong2 l1 = __ldg(reinterpret_cast<const ulonglong2*>(pr + ro + xb));
            ulonglong2 l2 = __ldg(reinterpret_cast<const ulonglong2*>(pr + ro + xc));
            u64 vp[6] = { l0.x, l0.y, l1.x, l1.y, l2.x, l2.y };
#pragma unroll
            for (int dx = 0; dx < 5; ++dx) {
                u64 t0 = fma2_(vp[dx],     M1C, ccx[p]);
                u64 t1 = fma2_(vp[dx + 1], M1C, ccy[p]);
                d2[dx][0] = fma2_(t0, t0, d2[dx][0]);
                d2[dx][1] = fma2_(t1, t1, d2[dx][1]);
            }
        }

        // ---- weights ----
        u64 w[5][2];
        const u64 mrow = pack2_(mr, mr);
#pragma unroll
        for (int dx = 0; dx < 5; ++dx) {
            float2 a = unpack2_(d2[dx][0]);
            float2 c = unpack2_(d2[dx][1]);
            u64 e0 = mul2_(pack2_(__expf(-a.x), __expf(-a.y)), mul2_(mX[dx][0], mrow));
            u64 e1 = mul2_(pack2_(__expf(-c.x), __expf(-c.y)), mul2_(mX[dx][1], mrow));
            w[dx][0] = e0;
            w[dx][1] = e1;
            ws0 = add2_(ws0, e0);
            ws1 = add2_(ws1, e1);
        }

        // ---- 24-channel accumulate from SMEM (conflict-free LDS.128) ----
#pragma unroll
        for (int ch = 0; ch < COUT; ++ch) {
            const float* sp = sm + (ch * KR + k) * PITCH + lane * 4;   // local col of x0-4
            ulonglong2 l0 = *reinterpret_cast<const ulonglong2*>(sp);
            ulonglong2 l1 = *reinterpret_cast<const ulonglong2*>(sp + 4);
            ulonglong2 l2 = *reinterpret_cast<const ulonglong2*>(sp + 8);
            u64 vp[6] = { l0.x, l0.y, l1.x, l1.y, l2.x, l2.y };
#pragma unroll
            for (int dx = 0; dx < 5; ++dx) {
                acc[ch][0] = fma2_(w[dx][0], vp[dx],     acc[ch][0]);
                acc[ch][1] = fma2_(w[dx][1], vp[dx + 1], acc[ch][1]);
            }
        }
    }

    // ---- normalize once at the store ----
    float2 s0 = unpack2_(ws0), s1 = unpack2_(ws1);
    const u64 r0 = pack2_(__fdividef(1.0f, s0.x + 1e-8f),
                          __fdividef(1.0f, s0.y + 1e-8f));
    const u64 r1 = pack2_(__fdividef(1.0f, s1.x + 1e-8f),
                          __fdividef(1.0f, s1.y + 1e-8f));

#pragma unroll
    for (int ch = 0; ch < COUT; ++ch) {
        float2 f0 = unpack2_(mul2_(acc[ch][0], r0));
        float2 f1 = unpack2_(mul2_(acc[ch][1], r1));
        *reinterpret_cast<float4*>(outb + ch * HWSZ + cbase) =
            make_float4(f0.x, f0.y, f1.x, f1.y);
    }
}

extern "C" void kernel_launch(void* const* d_in, const int* in_sizes, int n_in,
                              void* d_out, int out_size)
{
    const float* inp = (const float*)d_in[0];   // (4,32,512,512) f32
    const float* par = (const float*)d_in[1];   // (4, 8,512,512) f32
    if (n_in >= 2 && in_sizes[0] < in_sizes[1]) {
        const float* t = inp; inp = par; par = t;
    }
    float* out = (float*)d_out;                 // (4,24,512,512) f32

    cudaFuncSetAttribute(bilat_kernel,
                         cudaFuncAttributeMaxDynamicSharedMemorySize, SMEM_BYTES);

    dim3 grid(WW / 128, HH / RPC, 4);           // 4 x 64 x 4 = 1024 CTAs
    dim3 block(256);
    bilat_kernel<<<grid, block, SMEM_BYTES>>>(inp, par, out);
}

// round 14
// speedup vs baseline: 1.6882x; 1.0645x over previous
#include <cuda_runtime.h>

#define HH    512
#define WW    512
#define HWSZ  (HH * WW)
#define CIN   32
#define COUT  24
#define NP    8
#define RPC   8              // output rows per CTA
#define KR    16             // staged input rows per CTA
#define PITCH 140            // 4 pad floats + 136 data floats per staged row
#define ROWB  544            // bulk-copied bytes per row (136 floats)
#define DATA0 32             // float offset of staged data (after 128B mbar head)
#define NROWS (COUT * KR)    // 384 staged rows
#define SMEM_BYTES (DATA0 * 4 + NROWS * PITCH * 4 + 16)

typedef unsigned long long u64;

__device__ __forceinline__ u64 fma2_(u64 a, u64 b, u64 c) {
    u64 d; asm("fma.rn.f32x2 %0, %1, %2, %3;" : "=l"(d) : "l"(a), "l"(b), "l"(c)); return d;
}
__device__ __forceinline__ u64 add2_(u64 a, u64 b) {
    u64 d; asm("add.rn.f32x2 %0, %1, %2;" : "=l"(d) : "l"(a), "l"(b)); return d;
}
__device__ __forceinline__ u64 mul2_(u64 a, u64 b) {
    u64 d; asm("mul.rn.f32x2 %0, %1, %2;" : "=l"(d) : "l"(a), "l"(b)); return d;
}
__device__ __forceinline__ u64 pack2_(float lo, float hi) {
    u64 r; asm("mov.b64 %0, {%1, %2};" : "=l"(r) : "f"(lo), "f"(hi)); return r;
}
__device__ __forceinline__ float2 unpack2_(u64 v) {
    float lo, hi; asm("mov.b64 {%0, %1}, %2;" : "=f"(lo), "=f"(hi) : "l"(v));
    return make_float2(lo, hi);
}
__device__ __forceinline__ void mbar_wait(unsigned mbar, unsigned parity) {
    asm volatile(
        "{\n\t.reg .pred P;\n\t"
        "W%=:\n\t"
        "mbarrier.try_wait.parity.acquire.cta.shared::cta.b64 P, [%0], %1, 0x989680;\n\t"
        "@P bra.uni D%=;\n\t"
        "bra.uni W%=;\n\t"
        "D%=:\n\t}"
        :: "r"(mbar), "r"(parity) : "memory");
}

#define M1C 0xBF800000BF800000ull   /* (-1.0f, -1.0f) */

// Channel stream staged in SMEM via cp.async.bulk (1 UBLKCP per 544B row,
// ~1.5 instr/thread, mbarrier completion -- no LSU/scoreboard cost), fills
// OVERLAPPED with the whole weight phase (param LDG + d2 + exp). Channels
// then consumed as conflict-free LDS.128 (29 cyc, fully covered), 12 ch per
// half so acc fits registers. Front-pad keeps all LDS 16B-aligned; pads and
// tail zeroed so masked taps read 0.0 (never garbage/NaN).
__global__ void __launch_bounds__(256) bilat_kernel(
    const float* __restrict__ inp, const float* __restrict__ par,
    float* __restrict__ out)
{
    extern __shared__ float sm[];
    float* dat = sm + DATA0;

    const int tid   = threadIdx.x;
    const int lane  = tid & 31;
    const int wid   = tid >> 5;
    const int tileX = blockIdx.x * 128;
    const int x0    = tileX + lane * 4;
    const int y0    = blockIdx.y * RPC;
    const int y     = y0 + wid;
    const int b     = blockIdx.z;

    const float* __restrict__ parb = par + b * (NP * HWSZ);
    const float* __restrict__ inpb = inp + b * (CIN * HWSZ);
    float* __restrict__ outb = out + b * (COUT * HWSZ);

    const unsigned sbase = (unsigned)__cvta_generic_to_shared(sm);
    const unsigned mbar0 = sbase;
    const unsigned mbar1 = sbase + 8;

    // staged-row global x origin (fixed, in-bounds, 16B-aligned)
    const int gsrc = min(max(tileX - 4, 0), WW - 136);
    const int cofs = x0 - gsrc;          // consumer float offset within row data

    // ---- zero the 4-float pads (front of each staged row) + tail ----
    {
        const float4 z = make_float4(0.f, 0.f, 0.f, 0.f);
        for (int i = tid; i < NROWS; i += 256)
            *reinterpret_cast<float4*>(dat + i * PITCH) = z;
        if (tid == 0)
            *reinterpret_cast<float4*>(dat + NROWS * PITCH) = z;
    }
    if (tid == 0) {
        asm volatile("mbarrier.init.shared.b64 [%0], 1;" :: "r"(mbar0) : "memory");
        asm volatile("mbarrier.init.shared.b64 [%0], 1;" :: "r"(mbar1) : "memory");
        asm volatile("mbarrier.arrive.expect_tx.shared.b64 _, [%0], %1;"
                     :: "r"(mbar0), "r"(12 * KR * ROWB) : "memory");
        asm volatile("mbarrier.arrive.expect_tx.shared.b64 _, [%0], %1;"
                     :: "r"(mbar1), "r"(12 * KR * ROWB) : "memory");
    }
    __syncthreads();   // pads visible; mbarriers initialized before any bulk

    // ---- issue all bulk fills (384 rows; thread i handles rows i, i+256) ----
#pragma unroll
    for (int it = 0; it < 2; ++it) {
        const int i = tid + it * 256;
        if (i < NROWS) {
            const int ch  = i >> 4;
            const int row = i & 15;
            const int gy  = min(max(y0 - 4 + row, 0), HH - 1);
            const float* src = inpb + ch * HWSZ + gy * WW + gsrc;
            const unsigned dst = sbase + (unsigned)((DATA0 + i * PITCH + 4) * 4);
            const unsigned mb  = (ch < 12) ? mbar0 : mbar1;
            asm volatile(
                "cp.async.bulk.shared::cta.global.mbarrier::complete_tx::bytes "
                "[%0], [%1], %2, [%3];"
                :: "r"(dst), "l"(src), "r"(ROWB), "r"(mb) : "memory");
        }
    }

    // ================= WEIGHT PHASE (overlaps the fills) =================
    const int cbase = y * WW + x0;
    const int xa = max(x0 - 4, 0);
    const int xb = x0;
    const int xc = min(x0 + 4, WW - 4);

    u64 ccx[NP], ccy[NP];
#pragma unroll
    for (int p = 0; p < NP; ++p) {
        ulonglong2 cc = __ldg(reinterpret_cast<const ulonglong2*>(parb + p * HWSZ + cbase));
        ccx[p] = cc.x; ccy[p] = cc.y;
    }

    u64 w[5][5][2];
    u64 ws0 = 0ull, ws1 = 0ull;

#pragma unroll
    for (int dy = 0; dy < 5; ++dy) {
        const int   ny = y + dy * 2 - 4;
        const float mr = ((unsigned)ny < (unsigned)HH) ? 1.0f : 0.0f;
        const int   ro = min(max(ny, 0), HH - 1) * WW;

        u64 d2[5][2];
#pragma unroll
        for (int dx = 0; dx < 5; ++dx) { d2[dx][0] = 0ull; d2[dx][1] = 0ull; }

#pragma unroll
        for (int p = 0; p < NP; ++p) {
            const float* pr = parb + p * HWSZ;
            ulonglong2 l0 = __ldg(reinterpret_cast<const ulonglong2*>(pr + ro + xa));
            ulonglong2 l1 = __ldg(reinterpret_cast<const ulonglong2*>(pr + ro + xb));
            ulonglong2 l2 = __ldg(reinterpret_cast<const ulonglong2*>(pr + ro + xc));
            u64 vp[6] = { l0.x, l0.y, l1.x, l1.y, l2.x, l2.y };
#pragma unroll
            for (int dx = 0; dx < 5; ++dx) {
                u64 t0 = fma2_(vp[dx],     M1C, ccx[p]);
                u64 t1 = fma2_(vp[dx + 1], M1C, ccy[p]);
                d2[dx][0] = fma2_(t0, t0, d2[dx][0]);
                d2[dx][1] = fma2_(t1, t1, d2[dx][1]);
            }
        }

        const u64 mrow = pack2_(mr, mr);
#pragma unroll
        for (int dx = 0; dx < 5; ++dx) {
            const int g = x0 + dx * 2 - 4;
            const u64 mA = mul2_(pack2_(((unsigned)(g + 0) < (unsigned)WW) ? 1.0f : 0.0f,
                                        ((unsigned)(g + 1) < (unsigned)WW) ? 1.0f : 0.0f), mrow);
            const u64 mB = mul2_(pack2_(((unsigned)(g + 2) < (unsigned)WW) ? 1.0f : 0.0f,
                                        ((unsigned)(g + 3) < (unsigned)WW) ? 1.0f : 0.0f), mrow);
            float2 a = unpack2_(d2[dx][0]);
            float2 c = unpack2_(d2[dx][1]);
            u64 e0 = mul2_(pack2_(__expf(-a.x), __expf(-a.y)), mA);
            u64 e1 = mul2_(pack2_(__expf(-c.x), __expf(-c.y)), mB);
            w[dy][dx][0] = e0;
            w[dy][dx][1] = e1;
            ws0 = add2_(ws0, e0);
            ws1 = add2_(ws1, e1);
        }
    }

    float2 s0 = unpack2_(ws0), s1 = unpack2_(ws1);
    const u64 r0 = pack2_(__fdividef(1.0f, s0.x + 1e-8f),
                          __fdividef(1.0f, s0.y + 1e-8f));
    const u64 r1 = pack2_(__fdividef(1.0f, s1.x + 1e-8f),
                          __fdividef(1.0f, s1.y + 1e-8f));

    // ================= CHANNEL PHASE (two smem halves) =================
#pragma unroll
    for (int half = 0; half < 2; ++half) {
        mbar_wait(half ? mbar1 : mbar0, 0);

        u64 acc[12][2];
#pragma unroll
        for (int c = 0; c < 12; ++c) { acc[c][0] = 0ull; acc[c][1] = 0ull; }

#pragma unroll
        for (int ch = 0; ch < 12; ++ch) {
            const float* base = dat + ((half * 12 + ch) * KR) * PITCH + cofs;
#pragma unroll
            for (int dy = 0; dy < 5; ++dy) {
                const float* sp = base + (wid + 2 * dy) * PITCH;
                ulonglong2 l0 = *reinterpret_cast<const ulonglong2*>(sp);
                ulonglong2 l1 = *reinterpret_cast<const ulonglong2*>(sp + 4);
                ulonglong2 l2 = *reinterpret_cast<const ulonglong2*>(sp + 8);
                u64 vp[6] = { l0.x, l0.y, l1.x, l1.y, l2.x, l2.y };
#pragma unroll
                for (int dx = 0; dx < 5; ++dx) {
                    acc[ch][0] = fma2_(w[dy][dx][0], vp[dx],     acc[ch][0]);
                    acc[ch][1] = fma2_(w[dy][dx][1], vp[dx + 1], acc[ch][1]);
                }
            }
        }

#pragma unroll
        for (int ch = 0; ch < 12; ++ch) {
            float2 f0 = unpack2_(mul2_(acc[ch][0], r0));
            float2 f1 = unpack2_(mul2_(acc[ch][1], r1));
            *reinterpret_cast<float4*>(outb + (half * 12 + ch) * HWSZ + cbase) =
                make_float4(f0.x, f0.y, f1.x, f1.y);
        }
    }
}

extern "C" void kernel_launch(void* const* d_in, const int* in_sizes, int n_in,
                              void* d_out, int out_size)
{
    const float* inp = (const float*)d_in[0];   // (4,32,512,512) f32
    const float* par = (const float*)d_in[1];   // (4, 8,512,512) f32
    if (n_in >= 2 && in_sizes[0] < in_sizes[1]) {
        const float* t = inp; inp = par; par = t;
    }
    float* out = (float*)d_out;                 // (4,24,512,512) f32

    cudaFuncSetAttribute(bilat_kernel,
                         cudaFuncAttributeMaxDynamicSharedMemorySize, SMEM_BYTES);

    dim3 grid(WW / 128, HH / RPC, 4);           // 4 x 64 x 4 = 1024 CTAs
    dim3 block(256);
    bilat_kernel<<<grid, block, SMEM_BYTES>>>(inp, par, out);
}

// round 15
// speedup vs baseline: 1.7900x; 1.0603x over previous
#include <cuda_runtime.h>

#define HH    512
#define WW    512
#define HWSZ  (HH * WW)
#define CIN   32
#define COUT  24
#define NP    8
#define RPC   8              // output rows per CTA (warp = row)
#define KR    16             // staged input rows per CTA
#define PITCH 140            // 4 pad floats + 136 data floats per staged row
#define ROWB  544            // bulk-copied bytes per row
#define DATA0 32             // float offset of staged data (after mbar head)
#define NROWS (COUT * KR)    // 384 staged rows
#define SMEM_BYTES (DATA0 * 4 + NROWS * PITCH * 4 + 16)

typedef unsigned long long u64;

__device__ __forceinline__ u64 fma2_(u64 a, u64 b, u64 c) {
    u64 d; asm("fma.rn.f32x2 %0, %1, %2, %3;" : "=l"(d) : "l"(a), "l"(b), "l"(c)); return d;
}
__device__ __forceinline__ u64 add2_(u64 a, u64 b) {
    u64 d; asm("add.rn.f32x2 %0, %1, %2;" : "=l"(d) : "l"(a), "l"(b)); return d;
}
__device__ __forceinline__ u64 mul2_(u64 a, u64 b) {
    u64 d; asm("mul.rn.f32x2 %0, %1, %2;" : "=l"(d) : "l"(a), "l"(b)); return d;
}
__device__ __forceinline__ u64 pack2_(float lo, float hi) {
    u64 r; asm("mov.b64 %0, {%1, %2};" : "=l"(r) : "f"(lo), "f"(hi)); return r;
}
__device__ __forceinline__ float2 unpack2_(u64 v) {
    float lo, hi; asm("mov.b64 {%0, %1}, %2;" : "=f"(lo), "=f"(hi) : "l"(v));
    return make_float2(lo, hi);
}
__device__ __forceinline__ void mbar_wait(unsigned mbar, unsigned parity) {
    asm volatile(
        "{\n\t.reg .pred P;\n\t"
        "W%=:\n\t"
        "mbarrier.try_wait.parity.acquire.cta.shared::cta.b64 P, [%0], %1, 0x989680;\n\t"
        "@P bra.uni D%=;\n\t"
        "bra.uni W%=;\n\t"
        "D%=:\n\t}"
        :: "r"(mbar), "r"(parity) : "memory");
}

#define M1C 0xBF800000BF800000ull   /* (-1.0f, -1.0f) */

// R6's FUSED loop (params LDG -> d2 -> exp -> ephemeral w -> 24-ch FMA, per
// dy, fully unrolled: the FMA block covers the param-load latency) with the
// channel stream staged in SMEM by cp.async.bulk issued all up front (no
// register destinations -> outstanding-bytes beyond the RF cap). Channels
// become 29-cyc conflict-free LDS.128 instead of ~600-cyc DRAM LDG. One
// mbarrier; the wait sits after dy0's weight compute. Front-pad keeps LDS
// 16B-aligned; pads/tail zeroed so masked taps read 0 (never NaN).
__global__ void __launch_bounds__(256) bilat_kernel(
    const float* __restrict__ inp, const float* __restrict__ par,
    float* __restrict__ out)
{
    extern __shared__ float sm[];
    float* dat = sm + DATA0;

    const int tid   = threadIdx.x;
    const int lane  = tid & 31;
    const int wid   = tid >> 5;
    const int tileX = blockIdx.x * 128;
    const int x0    = tileX + lane * 4;
    const int y0    = blockIdx.y * RPC;
    const int y     = y0 + wid;
    const int b     = blockIdx.z;

    const float* __restrict__ parb = par + b * (NP * HWSZ);
    const float* __restrict__ inpb = inp + b * (CIN * HWSZ);
    float* __restrict__ outb = out + b * (COUT * HWSZ);

    const unsigned sbase = (unsigned)__cvta_generic_to_shared(sm);
    const unsigned mbar0 = sbase;

    const int gsrc = min(max(tileX - 4, 0), WW - 136);  // staged-row x origin
    const int cofs = x0 - gsrc;                          // consumer offset

    // ---- zero front pads + tail (masked taps must read 0.0) ----
    {
        const float4 z = make_float4(0.f, 0.f, 0.f, 0.f);
        for (int i = tid; i < NROWS; i += 256)
            *reinterpret_cast<float4*>(dat + i * PITCH) = z;
        if (tid == 0)
            *reinterpret_cast<float4*>(dat + NROWS * PITCH) = z;
    }
    if (tid == 0) {
        asm volatile("mbarrier.init.shared.b64 [%0], 1;" :: "r"(mbar0) : "memory");
        asm volatile("mbarrier.arrive.expect_tx.shared.b64 _, [%0], %1;"
                     :: "r"(mbar0), "r"(NROWS * ROWB) : "memory");
    }
    __syncthreads();

    // ---- issue ALL bulk fills (rows tid, tid+256) ----
#pragma unroll
    for (int it = 0; it < 2; ++it) {
        const int i = tid + it * 256;
        if (i < NROWS) {
            const int ch  = i >> 4;
            const int row = i & 15;
            const int gy  = min(max(y0 - 4 + row, 0), HH - 1);
            const float* src = inpb + ch * HWSZ + gy * WW + gsrc;
            const unsigned dst = sbase + (unsigned)((DATA0 + i * PITCH + 4) * 4);
            asm volatile(
                "cp.async.bulk.shared::cta.global.mbarrier::complete_tx::bytes "
                "[%0], [%1], %2, [%3];"
                :: "r"(dst), "l"(src), "r"(ROWB), "r"(mbar0) : "memory");
        }
    }

    // ---- hoisted center params ----
    const int cbase = y * WW + x0;
    const int xa = max(x0 - 4, 0);
    const int xb = x0;
    const int xc = min(x0 + 4, WW - 4);

    u64 ccx[NP], ccy[NP];
#pragma unroll
    for (int p = 0; p < NP; ++p) {
        ulonglong2 cc = __ldg(reinterpret_cast<const ulonglong2*>(parb + p * HWSZ + cbase));
        ccx[p] = cc.x; ccy[p] = cc.y;
    }

    // x-direction OOB masks
    u64 mX[5][2];
#pragma unroll
    for (int dx = 0; dx < 5; ++dx) {
        const int g = x0 + dx * 2 - 4;
        mX[dx][0] = pack2_(((unsigned)(g + 0) < (unsigned)WW) ? 1.0f : 0.0f,
                           ((unsigned)(g + 1) < (unsigned)WW) ? 1.0f : 0.0f);
        mX[dx][1] = pack2_(((unsigned)(g + 2) < (unsigned)WW) ? 1.0f : 0.0f,
                           ((unsigned)(g + 3) < (unsigned)WW) ? 1.0f : 0.0f);
    }

    u64 acc[COUT][2];
#pragma unroll
    for (int c = 0; c < COUT; ++c) { acc[c][0] = 0ull; acc[c][1] = 0ull; }
    u64 ws0 = 0ull, ws1 = 0ull;

    // ================= FUSED MAIN LOOP =================
#pragma unroll
    for (int dy = 0; dy < 5; ++dy) {
        const int   ny = y + dy * 2 - 4;
        const float mr = ((unsigned)ny < (unsigned)HH) ? 1.0f : 0.0f;
        const int   ro = min(max(ny, 0), HH - 1) * WW;

        // ---- squared param distances (direct LDG; latency covered by FMA) ----
        u64 d2[5][2];
#pragma unroll
        for (int dx = 0; dx < 5; ++dx) { d2[dx][0] = 0ull; d2[dx][1] = 0ull; }

#pragma unroll
        for (int p = 0; p < NP; ++p) {
            const float* pr = parb + p * HWSZ;
            ulonglong2 l0 = __ldg(reinterpret_cast<const ulonglong2*>(pr + ro + xa));
            ulonglong2 l1 = __ldg(reinterpret_cast<const ulonglong2*>(pr + ro + xb));
            ulonglong2 l2 = __ldg(reinterpret_cast<const ulonglong2*>(pr + ro + xc));
            u64 vp[6] = { l0.x, l0.y, l1.x, l1.y, l2.x, l2.y };
#pragma unroll
            for (int dx = 0; dx < 5; ++dx) {
                u64 t0 = fma2_(vp[dx],     M1C, ccx[p]);
                u64 t1 = fma2_(vp[dx + 1], M1C, ccy[p]);
                d2[dx][0] = fma2_(t0, t0, d2[dx][0]);
                d2[dx][1] = fma2_(t1, t1, d2[dx][1]);
            }
        }

        // ---- ephemeral weights for this dy ----
        u64 w[5][2];
        const u64 mrow = pack2_(mr, mr);
#pragma unroll
        for (int dx = 0; dx < 5; ++dx) {
            float2 a = unpack2_(d2[dx][0]);
            float2 c = unpack2_(d2[dx][1]);
            u64 e0 = mul2_(pack2_(__expf(-a.x), __expf(-a.y)), mul2_(mX[dx][0], mrow));
            u64 e1 = mul2_(pack2_(__expf(-c.x), __expf(-c.y)), mul2_(mX[dx][1], mrow));
            w[dx][0] = e0;
            w[dx][1] = e1;
            ws0 = add2_(ws0, e0);
            ws1 = add2_(ws1, e1);
        }

        // fills complete before first channel consumption
        if (dy == 0) mbar_wait(mbar0, 0);

        // ---- 24-channel accumulate from SMEM (conflict-free LDS.128) ----
        const int k = wid + 2 * dy;             // staged row index
#pragma unroll
        for (int ch = 0; ch < COUT; ++ch) {
            const float* sp = dat + (ch * KR + k) * PITCH + cofs;
            ulonglong2 l0 = *reinterpret_cast<const ulonglong2*>(sp);
            ulonglong2 l1 = *reinterpret_cast<const ulonglong2*>(sp + 4);
            ulonglong2 l2 = *reinterpret_cast<const ulonglong2*>(sp + 8);
            u64 vp[6] = { l0.x, l0.y, l1.x, l1.y, l2.x, l2.y };
#pragma unroll
            for (int dx = 0; dx < 5; ++dx) {
                acc[ch][0] = fma2_(w[dx][0], vp[dx],     acc[ch][0]);
                acc[ch][1] = fma2_(w[dx][1], vp[dx + 1], acc[ch][1]);
            }
        }
    }

    // ---- normalize once at the store ----
    float2 s0 = unpack2_(ws0), s1 = unpack2_(ws1);
    const u64 r0 = pack2_(__fdividef(1.0f, s0.x + 1e-8f),
                          __fdividef(1.0f, s0.y + 1e-8f));
    const u64 r1 = pack2_(__fdividef(1.0f, s1.x + 1e-8f),
                          __fdividef(1.0f, s1.y + 1e-8f));

#pragma unroll
    for (int ch = 0; ch < COUT; ++ch) {
        float2 f0 = unpack2_(mul2_(acc[ch][0], r0));
        float2 f1 = unpack2_(mul2_(acc[ch][1], r1));
        *reinterpret_cast<float4*>(outb + ch * HWSZ + cbase) =
            make_float4(f0.x, f0.y, f1.x, f1.y);
    }
}

extern "C" void kernel_launch(void* const* d_in, const int* in_sizes, int n_in,
                              void* d_out, int out_size)
{
    const float* inp = (const float*)d_in[0];   // (4,32,512,512) f32
    const float* par = (const float*)d_in[1];   // (4, 8,512,512) f32
    if (n_in >= 2 && in_sizes[0] < in_sizes[1]) {
        const float* t = inp; inp = par; par = t;
    }
    float* out = (float*)d_out;                 // (4,24,512,512) f32

    cudaFuncSetAttribute(bilat_kernel,
                         cudaFuncAttributeMaxDynamicSharedMemorySize, SMEM_BYTES);

    dim3 grid(WW / 128, HH / RPC, 4);           // 4 x 64 x 4 = 1024 CTAs
    dim3 block(256);
    bilat_kernel<<<grid, block, SMEM_BYTES>>>(inp, par, out);
}